// round 2
// baseline (speedup 1.0000x reference)
#include <cuda_runtime.h>
#include <math.h>
#include <float.h>

// ---------------- problem constants ----------------
#define Bsz   8
#define Npts  2048
#define Kn    16
#define Hc    128
#define Lc    4
#define CDc   128
#define Jtot  (Bsz * Npts * 3)      // 49152 "vector rows" (b,n,d)
#define NBlk  (Bsz * Npts)          // 16384 (b,n) pairs
#define EPSf  1e-12f

// ---------------- scratch (static device globals; no allocs) ----------------
__device__ int   g_idx[NBlk * Kn];             // knn indices
__device__ float g_M3[Hc * 3];                 // Wd_in @ W_in
__device__ float g_Mw[Lc * Hc * Hc];           // Wds[i] @ Ws[i]
__device__ float g_MG[Lc * Hc * 2 * Hc];       // Gds[i] @ Gs[i]
__device__ float g_X0[Jtot * Hc];              // stage-2 output h (layer-0 input)
__device__ float g_U[Jtot * Hc];               // GEMM out: u
__device__ float g_Kr[Jtot * Hc];              // GEMM out: k-raw
__device__ float g_X2[Jtot * 2 * Hc];          // concat [h1 ; g]
__device__ float g_FEATS[Jtot * Lc * Hc];      // per-layer outputs, column blocks
__device__ float g_gmean[Bsz * 3 * Hc];        // per-batch mean over N (raw sum)

// ---------------- small helpers ----------------
__device__ __forceinline__ float blockReduceSum128(float v, float* sred) {
    #pragma unroll
    for (int o = 16; o > 0; o >>= 1) v += __shfl_xor_sync(0xffffffffu, v, o);
    int w = threadIdx.x >> 5;
    if ((threadIdx.x & 31) == 0) sred[w] = v;
    __syncthreads();
    float tot = sred[0] + sred[1] + sred[2] + sred[3];
    __syncthreads();
    return tot;
}

// ---------------- kernel: precompute fused weight products ----------------
// M3 = Wd_in @ W_in (Hx3); Mw[i] = Wds[i]@Ws[i] (HxH); MG[i] = Gds[i]@Gs[i] (Hx2H)
__global__ void prep_kernel(const float* __restrict__ W_in,
                            const float* __restrict__ Wd_in,
                            const float* __restrict__ Ws,
                            const float* __restrict__ Wds,
                            const float* __restrict__ Gs,
                            const float* __restrict__ Gds) {
    int t = blockIdx.x * blockDim.x + threadIdx.x;
    const int N3  = Hc * 3;                 // 384
    const int NMw = Lc * Hc * Hc;           // 65536
    const int NMG = Lc * Hc * 2 * Hc;       // 131072
    if (t < N3) {
        int o = t / 3, i = t % 3;
        float s = 0.f;
        #pragma unroll 8
        for (int c = 0; c < Hc; c++) s += Wd_in[o * Hc + c] * W_in[c * 3 + i];
        g_M3[t] = s;
    } else if (t < N3 + NMw) {
        int r = t - N3;
        int l = r >> 14;
        int o = (r >> 7) & 127;
        int c2 = r & 127;
        const float* wd = Wds + l * Hc * Hc + o * Hc;
        const float* w  = Ws  + l * Hc * Hc;
        float s = 0.f;
        #pragma unroll 8
        for (int c = 0; c < Hc; c++) s += wd[c] * w[c * Hc + c2];
        g_Mw[r] = s;
    } else if (t < N3 + NMw + NMG) {
        int r = t - N3 - NMw;
        int l = r >> 15;
        int rem = r & 32767;
        int o = rem >> 8;
        int c2 = rem & 255;
        const float* gd = Gds + l * Hc * Hc + o * Hc;
        const float* g  = Gs  + l * Hc * 2 * Hc;
        float s = 0.f;
        #pragma unroll 8
        for (int c = 0; c < Hc; c++) s += gd[c] * g[c * 2 * Hc + c2];
        g_MG[r] = s;
    }
}

// ---------------- kernel: kNN (K=16 smallest d2, self included) ----------------
// x layout: (B, 3, N). One block = 256 queries of one batch.
__global__ void knn_kernel(const float* __restrict__ x) {
    __shared__ float4 spts[Npts];           // xyz + |p|^2, 32KB
    int b = blockIdx.x >> 3;
    int chunk = blockIdx.x & 7;
    const float* xb = x + b * 3 * Npts;
    for (int i = threadIdx.x; i < Npts; i += 256) {
        float px = xb[i], py = xb[Npts + i], pz = xb[2 * Npts + i];
        spts[i] = make_float4(px, py, pz, px * px + py * py + pz * pz);
    }
    __syncthreads();
    int q = chunk * 256 + threadIdx.x;
    float4 Q = spts[q];
    float bd[Kn]; int bi[Kn];
    #pragma unroll
    for (int t = 0; t < Kn; t++) { bd[t] = FLT_MAX; bi[t] = 0; }
    float worst = FLT_MAX; int wslot = 0;
    for (int m = 0; m < Npts; m++) {
        float4 P = spts[m];
        float d2 = Q.w + P.w - 2.f * (Q.x * P.x + Q.y * P.y + Q.z * P.z);
        if (d2 < worst) {
            #pragma unroll
            for (int t = 0; t < Kn; t++) if (t == wslot) { bd[t] = d2; bi[t] = m; }
            worst = bd[0]; wslot = 0;
            #pragma unroll
            for (int t = 1; t < Kn; t++) if (bd[t] > worst) { worst = bd[t]; wslot = t; }
        }
    }
    int base = (b * Npts + q) * Kn;
    #pragma unroll
    for (int t = 0; t < Kn; t++) g_idx[base + t] = bi[t];
}

// ---------------- kernel: fused edge stage ----------------
// For each (b,n): loop K neighbors, build y = [cross(x_dir,nbr), nbr-x, x],
// u = W_in@y, kr = M3@y, normalize+activate, mean over K -> g_X0 (J x H).
__global__ void stage2_kernel(const float* __restrict__ x,
                              const float* __restrict__ W_in) {
    __shared__ float3 snbr[Kn];
    __shared__ float sred[4];
    int bn = blockIdx.x;
    int b = bn >> 11, n = bn & 2047;
    int c = threadIdx.x;                    // 128 threads = channel
    const float* xb = x + b * 3 * Npts;
    float xnx = xb[n], xny = xb[Npts + n], xnz = xb[2 * Npts + n];
    float xl = sqrtf(xnx * xnx + xny * xny + xnz * xnz);
    float xinv = 1.f / fmaxf(xl, EPSf);
    float dxx = xnx * xinv, dxy = xny * xinv, dxz = xnz * xinv;
    if (c < Kn) {
        int m = g_idx[bn * Kn + c];
        snbr[c] = make_float3(xb[m], xb[Npts + m], xb[2 * Npts + m]);
    }
    __syncthreads();
    float w0 = W_in[c * 3 + 0], w1 = W_in[c * 3 + 1], w2 = W_in[c * 3 + 2];
    float m0 = g_M3[c * 3 + 0], m1 = g_M3[c * 3 + 1], m2 = g_M3[c * 3 + 2];
    float ax = 0.f, ay = 0.f, az = 0.f;
    for (int k = 0; k < Kn; k++) {
        float3 p = snbr[k];
        // y0 = cross(x_dir, nbr)
        float c0x = dxy * p.z - dxz * p.y;
        float c0y = dxz * p.x - dxx * p.z;
        float c0z = dxx * p.y - dxy * p.x;
        // y1 = nbr - x ; y2 = x
        float e1x = p.x - xnx, e1y = p.y - xny, e1z = p.z - xnz;
        float ux = w0 * c0x + w1 * e1x + w2 * xnx;
        float uy = w0 * c0y + w1 * e1y + w2 * xny;
        float uz = w0 * c0z + w1 * e1z + w2 * xnz;
        float kx = m0 * c0x + m1 * e1x + m2 * xnx;
        float ky = m0 * c0y + m1 * e1y + m2 * xny;
        float kz = m0 * c0z + m1 * e1z + m2 * xnz;
        float tot = blockReduceSum128(ux * ux + uy * uy + uz * uz, sred);
        float s = 1.f / fmaxf(sqrtf(tot), EPSf);
        float kl = sqrtf(kx * kx + ky * ky + kz * kz);
        float ki = 1.f / fmaxf(kl, EPSf);
        kx *= ki; ky *= ki; kz *= ki;
        float dot = s * (ux * kx + uy * ky + uz * kz);
        float neg = fminf(dot, 0.f);
        ax += s * ux - neg * kx;
        ay += s * uy - neg * ky;
        az += s * uz - neg * kz;
    }
    const float invK = 1.f / (float)Kn;
    int j0 = bn * 3;
    g_X0[(j0 + 0) * Hc + c] = ax * invK;
    g_X0[(j0 + 1) * Hc + c] = ay * invK;
    g_X0[(j0 + 2) * Hc + c] = az * invK;
}

// ---------------- kernel: SGEMM  C[j][o] = sum_c A[j*lda+c] * W[o*Cin+c] ----------------
// C is J x 128 row-major (ldc = 128). grid.x = J/128.
#define BM 128
#define BN 128
#define BK 8
__global__ __launch_bounds__(256) void gemm_nt(const float* __restrict__ A, int lda,
                                               const float* __restrict__ W, int Cin,
                                               float* __restrict__ C) {
    __shared__ __align__(16) float As[BK][BM];
    __shared__ __align__(16) float Bs[BK][BN];
    int tid = threadIdx.x;
    int jBase = blockIdx.x * BM;
    int tx = tid & 15, ty = tid >> 4;
    int rowA = tid >> 1;
    int kA = (tid & 1) * 4;
    float acc[8][8];
    #pragma unroll
    for (int i = 0; i < 8; i++)
        #pragma unroll
        for (int j = 0; j < 8; j++) acc[i][j] = 0.f;

    for (int k0 = 0; k0 < Cin; k0 += BK) {
        float4 a  = *(const float4*)(A + (size_t)(jBase + rowA) * lda + k0 + kA);
        float4 bb = *(const float4*)(W + (size_t)rowA * Cin + k0 + kA);
        As[kA + 0][rowA] = a.x;  As[kA + 1][rowA] = a.y;
        As[kA + 2][rowA] = a.z;  As[kA + 3][rowA] = a.w;
        Bs[kA + 0][rowA] = bb.x; Bs[kA + 1][rowA] = bb.y;
        Bs[kA + 2][rowA] = bb.z; Bs[kA + 3][rowA] = bb.w;
        __syncthreads();
        #pragma unroll
        for (int kk = 0; kk < BK; kk++) {
            float4 a0 = *(const float4*)&As[kk][ty * 8];
            float4 a1 = *(const float4*)&As[kk][ty * 8 + 4];
            float4 b0 = *(const float4*)&Bs[kk][tx * 8];
            float4 b1 = *(const float4*)&Bs[kk][tx * 8 + 4];
            float ar[8] = {a0.x, a0.y, a0.z, a0.w, a1.x, a1.y, a1.z, a1.w};
            float br[8] = {b0.x, b0.y, b0.z, b0.w, b1.x, b1.y, b1.z, b1.w};
            #pragma unroll
            for (int i = 0; i < 8; i++)
                #pragma unroll
                for (int j = 0; j < 8; j++) acc[i][j] += ar[i] * br[j];
        }
        __syncthreads();
    }
    #pragma unroll
    for (int i = 0; i < 8; i++) {
        int row = jBase + ty * 8 + i;
        float4* cp = (float4*)(C + (size_t)row * BN + tx * 8);
        cp[0] = make_float4(acc[i][0], acc[i][1], acc[i][2], acc[i][3]);
        cp[1] = make_float4(acc[i][4], acc[i][5], acc[i][6], acc[i][7]);
    }
}

// ---------------- kernel: vec_lna pointwise epilogue ----------------
// u, kr: (J x 128). dst[(j)*ldd + off + c] = s*u - min(dot,0)*k_dir
__global__ void pointwise_kernel(const float* __restrict__ U,
                                 const float* __restrict__ Kr,
                                 float* __restrict__ dst, int ldd, int off) {
    __shared__ float sred[4];
    int bn = blockIdx.x;
    int c = threadIdx.x;
    int j0 = bn * 3;
    float ux = U[(size_t)(j0 + 0) * Hc + c];
    float uy = U[(size_t)(j0 + 1) * Hc + c];
    float uz = U[(size_t)(j0 + 2) * Hc + c];
    float kx = Kr[(size_t)(j0 + 0) * Hc + c];
    float ky = Kr[(size_t)(j0 + 1) * Hc + c];
    float kz = Kr[(size_t)(j0 + 2) * Hc + c];
    float tot = blockReduceSum128(ux * ux + uy * uy + uz * uz, sred);
    float s = 1.f / fmaxf(sqrtf(tot), EPSf);
    float kl = sqrtf(kx * kx + ky * ky + kz * kz);
    float ki = 1.f / fmaxf(kl, EPSf);
    kx *= ki; ky *= ki; kz *= ki;
    float dot = s * (ux * kx + uy * ky + uz * kz);
    float neg = fminf(dot, 0.f);
    dst[(size_t)(j0 + 0) * ldd + off + c] = s * ux - neg * kx;
    dst[(size_t)(j0 + 1) * ldd + off + c] = s * uy - neg * ky;
    dst[(size_t)(j0 + 2) * ldd + off + c] = s * uz - neg * kz;
}

// ---------------- kernel: mean over N of h1 (cols 0..127 of g_X2) ----------------
__global__ void meanN_kernel() {
    int bd = blockIdx.x;                    // 0..23  (b*3+d)
    int b = bd / 3, d = bd % 3;
    int c = threadIdx.x;
    const float* base = g_X2 + ((size_t)(b * Npts) * 3 + d) * (2 * Hc) + c;
    float s = 0.f;
    #pragma unroll 8
    for (int n = 0; n < Npts; n++) s += base[(size_t)n * 3 * (2 * Hc)];
    g_gmean[bd * Hc + c] = s;
}

// broadcast mean into cols 128..255 of g_X2
__global__ void bcast_kernel() {
    int t = blockIdx.x * blockDim.x + threadIdx.x;  // Jtot*Hc threads
    int c = t & 127;
    int j = t >> 7;
    int b = j / (Npts * 3);
    int d = j % 3;
    g_X2[(size_t)j * (2 * Hc) + Hc + c] = g_gmean[(b * 3 + d) * Hc + c] * (1.f / (float)Npts);
}

// ---------------- kernel: final transpose write to output layout ----------------
// g_U holds OUT as (J x 128) = [(b,n,d)][o]; output wants (b, o, d, n).
__global__ void writeout_kernel(float* __restrict__ out, int big_off) {
    long long t = (long long)blockIdx.x * blockDim.x + threadIdx.x;
    int n = (int)(t & 2047);
    long long r = t >> 11;
    int d = (int)(r % 3); r /= 3;
    int o = (int)(r & 127);
    int b = (int)(r >> 7);
    out[big_off + t] = g_U[(((size_t)(b * Npts + n)) * 3 + d) * Hc + o];
}

// ---------------- kernel: mean over N of the output ----------------
__global__ void meanout_kernel(float* __restrict__ out, int big_off, int mean_off) {
    int w = blockIdx.x * 8 + (threadIdx.x >> 5);    // 3072 warps, one per (b,o,d)
    int lane = threadIdx.x & 31;
    const float* base = out + big_off + (size_t)w * Npts;
    float s = 0.f;
    #pragma unroll 8
    for (int i = lane; i < Npts; i += 32) s += base[i];
    #pragma unroll
    for (int o = 16; o > 0; o >>= 1) s += __shfl_xor_sync(0xffffffffu, s, o);
    if (lane == 0) out[mean_off + w] = s * (1.f / (float)Npts);
}

// ---------------- host launcher ----------------
extern "C" void kernel_launch(void* const* d_in, const int* in_sizes, int n_in,
                              void* d_out, int out_size) {
    const float* x     = (const float*)d_in[0];
    const float* W_in  = (const float*)d_in[1];
    const float* Wd_in = (const float*)d_in[2];
    const float* Ws    = (const float*)d_in[3];
    const float* Wds   = (const float*)d_in[4];
    const float* Gs    = (const float*)d_in[5];
    const float* Gds   = (const float*)d_in[6];
    const float* W_out = (const float*)d_in[7];
    float* out = (float*)d_out;

    float *pX0, *pU, *pKr, *pX2, *pFEATS, *pMw, *pMG;
    cudaGetSymbolAddress((void**)&pX0, g_X0);
    cudaGetSymbolAddress((void**)&pU, g_U);
    cudaGetSymbolAddress((void**)&pKr, g_Kr);
    cudaGetSymbolAddress((void**)&pX2, g_X2);
    cudaGetSymbolAddress((void**)&pFEATS, g_FEATS);
    cudaGetSymbolAddress((void**)&pMw, g_Mw);
    cudaGetSymbolAddress((void**)&pMG, g_MG);

    // output packing: (mean (B,CD,3), out (B,CD,3,N)) concatenated, or big only
    int mean_off = 0, big_off = 0;
    bool has_mean = true;
    const int BIG = Bsz * CDc * 3 * Npts;       // 6291456
    const int MEAN = Bsz * CDc * 3;             // 3072
    if (out_size >= BIG + MEAN) { mean_off = 0; big_off = MEAN; }
    else { big_off = 0; has_mean = false; }

    prep_kernel<<<(384 + Lc * Hc * Hc + Lc * Hc * 2 * Hc + 255) / 256, 256>>>(
        W_in, Wd_in, Ws, Wds, Gs, Gds);
    knn_kernel<<<Bsz * 8, 256>>>(x);
    stage2_kernel<<<NBlk, 128>>>(x, W_in);

    const float* Xi = pX0;
    int lda = Hc;
    const int gGrid = Jtot / BM;                // 384
    for (int i = 0; i < Lc; i++) {
        gemm_nt<<<gGrid, 256>>>(Xi, lda, Ws + (size_t)i * Hc * Hc, Hc, pU);
        gemm_nt<<<gGrid, 256>>>(Xi, lda, pMw + (size_t)i * Hc * Hc, Hc, pKr);
        pointwise_kernel<<<NBlk, 128>>>(pU, pKr, pX2, 2 * Hc, 0);
        meanN_kernel<<<Bsz * 3, 128>>>();
        bcast_kernel<<<(Jtot * Hc) / 256, 256>>>();
        gemm_nt<<<gGrid, 256>>>(pX2, 2 * Hc, Gs + (size_t)i * Hc * 2 * Hc, 2 * Hc, pU);
        gemm_nt<<<gGrid, 256>>>(pX2, 2 * Hc, pMG + (size_t)i * Hc * 2 * Hc, 2 * Hc, pKr);
        pointwise_kernel<<<NBlk, 128>>>(pU, pKr, pFEATS, Lc * Hc, i * Hc);
        Xi = pFEATS + i * Hc;
        lda = Lc * Hc;
    }
    // final projection: OUT = FEATS (J x 512) @ W_out^T (128 x 512)
    gemm_nt<<<gGrid, 256>>>(pFEATS, Lc * Hc, W_out, Lc * Hc, pU);
    writeout_kernel<<<(Jtot * Hc) / 256, 256>>>(out, big_off);
    if (has_mean) meanout_kernel<<<384, 256>>>(out, big_off, mean_off);
}

// round 4
// speedup vs baseline: 1.3773x; 1.3773x over previous
#include <cuda_runtime.h>
#include <cuda_bf16.h>
#include <math.h>
#include <float.h>
#include <stdint.h>

// ---------------- problem constants ----------------
#define Bsz   8
#define Npts  2048
#define Kn    16
#define Hc    128
#define Lc    4
#define CDc   128
#define Jtot  (Bsz * Npts * 3)      // 49152 "vector rows" (b,n,d)
#define NBlk  (Bsz * Npts)          // 16384 (b,n) pairs
#define EPSf  1e-12f

typedef __nv_bfloat16 bf16;

// ---------------- scratch (static device globals; no allocs) ----------------
__device__ int   g_idx[NBlk * Kn];
__device__ float g_M3[Hc * 3];                       // Wd_in @ W_in
// stacked+split weights
__device__ bf16  g_UKh[Lc * 256 * 128];              // [Ws ; Wds@Ws] hi
__device__ bf16  g_UKl[Lc * 256 * 128];
__device__ bf16  g_GWh[Lc * 256 * 256];              // [Gs ; Gds@Gs] hi
__device__ bf16  g_GWl[Lc * 256 * 256];
__device__ bf16  g_OWh[128 * 512];                   // W_out hi
__device__ bf16  g_OWl[128 * 512];
// split activations
__device__ bf16  g_X0h[Jtot * 128];
__device__ bf16  g_X0l[Jtot * 128];
__device__ bf16  g_X2h[Jtot * 256];
__device__ bf16  g_X2l[Jtot * 256];
__device__ bf16  g_FTh[Jtot * 512];
__device__ bf16  g_FTl[Jtot * 512];
__device__ float g_C[Jtot * 256];                    // GEMM output (fp32)
__device__ float g_gmean[Bsz * 3 * Hc];

// ---------------- helpers ----------------
__device__ __forceinline__ float blockReduceSum128(float v, float* sred) {
    #pragma unroll
    for (int o = 16; o > 0; o >>= 1) v += __shfl_xor_sync(0xffffffffu, v, o);
    int w = threadIdx.x >> 5;
    if ((threadIdx.x & 31) == 0) sred[w] = v;
    __syncthreads();
    float tot = sred[0] + sred[1] + sred[2] + sred[3];
    __syncthreads();
    return tot;
}

__device__ __forceinline__ void split2(float v, bf16& h, bf16& l) {
    h = __float2bfloat16(v);
    l = __float2bfloat16(v - __bfloat162float(h));
}

__device__ __forceinline__ uint32_t smem_u32(const void* p) {
    uint32_t r;
    asm("{ .reg .u64 t; cvta.to.shared.u64 t, %1; cvt.u32.u64 %0, t; }"
        : "=r"(r) : "l"(p));
    return r;
}

__device__ __forceinline__ void ldsm_x4(uint32_t& r0, uint32_t& r1,
                                        uint32_t& r2, uint32_t& r3, uint32_t addr) {
    asm volatile("ldmatrix.sync.aligned.m8n8.x4.shared.b16 {%0,%1,%2,%3}, [%4];"
                 : "=r"(r0), "=r"(r1), "=r"(r2), "=r"(r3) : "r"(addr));
}

__device__ __forceinline__ void ldsm_x2(uint32_t& r0, uint32_t& r1, uint32_t addr) {
    asm volatile("ldmatrix.sync.aligned.m8n8.x2.shared.b16 {%0,%1}, [%2];"
                 : "=r"(r0), "=r"(r1) : "r"(addr));
}

__device__ __forceinline__ void mma16816(float* d, const uint32_t* a, const uint32_t* b) {
    asm volatile("mma.sync.aligned.m16n8k16.row.col.f32.bf16.bf16.f32 "
                 "{%0,%1,%2,%3}, {%4,%5,%6,%7}, {%8,%9}, {%0,%1,%2,%3};"
                 : "+f"(d[0]), "+f"(d[1]), "+f"(d[2]), "+f"(d[3])
                 : "r"(a[0]), "r"(a[1]), "r"(a[2]), "r"(a[3]),
                   "r"(b[0]), "r"(b[1]));
}

// global prefetch for one BK=32 slab of the extended-K bf16x3 GEMM
__device__ __forceinline__ void gload(int it, int Cin, int lda,
                                      const bf16* Ah, const bf16* Al,
                                      const bf16* Wh, const bf16* Wl,
                                      int jBase, int nBase, int ar, int ac,
                                      uint4& pa0, uint4& pa1,
                                      uint4& pb0, uint4& pb1) {
    int k0 = it << 5;
    int seg = k0 / Cin;
    int kin = k0 - seg * Cin;
    const bf16* Ap = (seg == 1) ? Al : Ah;
    const bf16* Bp = (seg == 2) ? Wl : Wh;
    const bf16* arow = Ap + (size_t)(jBase + ar) * lda + kin + ac * 8;
    pa0 = *(const uint4*)(arow);
    pa1 = *(const uint4*)(arow + 8);
    const bf16* brow = Bp + (size_t)(nBase + ar) * Cin + kin + ac * 8;
    pb0 = *(const uint4*)(brow);
    pb1 = *(const uint4*)(brow + 8);
}

// ---------------- prep: fused+stacked+split weights ----------------
__global__ void prep_kernel(const float* __restrict__ W_in,
                            const float* __restrict__ Wd_in,
                            const float* __restrict__ Ws,
                            const float* __restrict__ Wds,
                            const float* __restrict__ Gs,
                            const float* __restrict__ Gds,
                            const float* __restrict__ W_out) {
    int t = blockIdx.x * blockDim.x + threadIdx.x;
    const int N3  = Hc * 3;                 // 384
    const int NUK = Lc * 256 * 128;         // 131072
    const int NGW = Lc * 256 * 256;         // 262144
    const int NOW = 128 * 512;              // 65536
    if (t < N3) {
        int o = t / 3, i = t % 3;
        float s = 0.f;
        #pragma unroll 8
        for (int c = 0; c < Hc; c++) s += Wd_in[o * Hc + c] * W_in[c * 3 + i];
        g_M3[t] = s;
    } else if (t < N3 + NUK) {
        int r = t - N3;
        int l = r >> 15;
        int o = (r >> 7) & 255;
        int c = r & 127;
        float v;
        if (o < 128) {
            v = Ws[l * Hc * Hc + o * Hc + c];
        } else {
            const float* wd = Wds + l * Hc * Hc + (o - 128) * Hc;
            const float* w  = Ws  + l * Hc * Hc;
            float s = 0.f;
            #pragma unroll 8
            for (int cc = 0; cc < Hc; cc++) s += wd[cc] * w[cc * Hc + c];
            v = s;
        }
        split2(v, g_UKh[r], g_UKl[r]);
    } else if (t < N3 + NUK + NGW) {
        int r = t - N3 - NUK;
        int l = r >> 16;
        int o = (r >> 8) & 255;
        int c = r & 255;
        float v;
        if (o < 128) {
            v = Gs[l * Hc * 2 * Hc + o * 2 * Hc + c];
        } else {
            const float* gd = Gds + l * Hc * Hc + (o - 128) * Hc;
            const float* g  = Gs  + l * Hc * 2 * Hc;
            float s = 0.f;
            #pragma unroll 8
            for (int cc = 0; cc < Hc; cc++) s += gd[cc] * g[cc * 2 * Hc + c];
            v = s;
        }
        split2(v, g_GWh[r], g_GWl[r]);
    } else if (t < N3 + NUK + NGW + NOW) {
        int r = t - N3 - NUK - NGW;
        split2(W_out[r], g_OWh[r], g_OWl[r]);
    }
}

// ---------------- kNN ----------------
__global__ void knn_kernel(const float* __restrict__ x) {
    __shared__ float4 spts[Npts];
    int b = blockIdx.x >> 3;
    int chunk = blockIdx.x & 7;
    const float* xb = x + b * 3 * Npts;
    for (int i = threadIdx.x; i < Npts; i += 256) {
        float px = xb[i], py = xb[Npts + i], pz = xb[2 * Npts + i];
        spts[i] = make_float4(px, py, pz, px * px + py * py + pz * pz);
    }
    __syncthreads();
    int q = chunk * 256 + threadIdx.x;
    float4 Q = spts[q];
    float bd[Kn]; int bi[Kn];
    #pragma unroll
    for (int t = 0; t < Kn; t++) { bd[t] = FLT_MAX; bi[t] = 0; }
    float worst = FLT_MAX; int wslot = 0;
    for (int m = 0; m < Npts; m++) {
        float4 P = spts[m];
        float d2 = Q.w + P.w - 2.f * (Q.x * P.x + Q.y * P.y + Q.z * P.z);
        if (d2 < worst) {
            #pragma unroll
            for (int t = 0; t < Kn; t++) if (t == wslot) { bd[t] = d2; bi[t] = m; }
            worst = bd[0]; wslot = 0;
            #pragma unroll
            for (int t = 1; t < Kn; t++) if (bd[t] > worst) { worst = bd[t]; wslot = t; }
        }
    }
    int base = (b * Npts + q) * Kn;
    #pragma unroll
    for (int t = 0; t < Kn; t++) g_idx[base + t] = bi[t];
}

// ---------------- fused edge stage -> X0 split ----------------
__global__ void stage2_kernel(const float* __restrict__ x,
                              const float* __restrict__ W_in) {
    __shared__ float3 snbr[Kn];
    __shared__ float sred[4];
    int bn = blockIdx.x;
    int b = bn >> 11, n = bn & 2047;
    int c = threadIdx.x;
    const float* xb = x + b * 3 * Npts;
    float xnx = xb[n], xny = xb[Npts + n], xnz = xb[2 * Npts + n];
    float xl = sqrtf(xnx * xnx + xny * xny + xnz * xnz);
    float xinv = 1.f / fmaxf(xl, EPSf);
    float dxx = xnx * xinv, dxy = xny * xinv, dxz = xnz * xinv;
    if (c < Kn) {
        int m = g_idx[bn * Kn + c];
        snbr[c] = make_float3(xb[m], xb[Npts + m], xb[2 * Npts + m]);
    }
    __syncthreads();
    float w0 = W_in[c * 3 + 0], w1 = W_in[c * 3 + 1], w2 = W_in[c * 3 + 2];
    float m0 = g_M3[c * 3 + 0], m1 = g_M3[c * 3 + 1], m2 = g_M3[c * 3 + 2];
    float ax = 0.f, ay = 0.f, az = 0.f;
    for (int k = 0; k < Kn; k++) {
        float3 p = snbr[k];
        float c0x = dxy * p.z - dxz * p.y;
        float c0y = dxz * p.x - dxx * p.z;
        float c0z = dxx * p.y - dxy * p.x;
        float e1x = p.x - xnx, e1y = p.y - xny, e1z = p.z - xnz;
        float ux = w0 * c0x + w1 * e1x + w2 * xnx;
        float uy = w0 * c0y + w1 * e1y + w2 * xny;
        float uz = w0 * c0z + w1 * e1z + w2 * xnz;
        float kx = m0 * c0x + m1 * e1x + m2 * xnx;
        float ky = m0 * c0y + m1 * e1y + m2 * xny;
        float kz = m0 * c0z + m1 * e1z + m2 * xnz;
        float tot = blockReduceSum128(ux * ux + uy * uy + uz * uz, sred);
        float s = 1.f / fmaxf(sqrtf(tot), EPSf);
        float kl = sqrtf(kx * kx + ky * ky + kz * kz);
        float ki = 1.f / fmaxf(kl, EPSf);
        kx *= ki; ky *= ki; kz *= ki;
        float dot = s * (ux * kx + uy * ky + uz * kz);
        float neg = fminf(dot, 0.f);
        ax += s * ux - neg * kx;
        ay += s * uy - neg * ky;
        az += s * uz - neg * kz;
    }
    const float invK = 1.f / (float)Kn;
    int j0 = bn * 3;
    split2(ax * invK, g_X0h[(size_t)(j0 + 0) * Hc + c], g_X0l[(size_t)(j0 + 0) * Hc + c]);
    split2(ay * invK, g_X0h[(size_t)(j0 + 1) * Hc + c], g_X0l[(size_t)(j0 + 1) * Hc + c]);
    split2(az * invK, g_X0h[(size_t)(j0 + 2) * Hc + c], g_X0l[(size_t)(j0 + 2) * Hc + c]);
}

// ---------------- bf16x3 tensor-core GEMM ----------------
// C[j][n] = sum_c A[j,c]*W[n,c], A = Ah+Al (bf16 split, row pitch lda),
// W = Wh+Wl (row-major, pitch Cin). Extended K' = 3*Cin: (Ah,Wh),(Al,Wh),(Ah,Wl).
// BM=128, BN=128, BK=32, 256 threads (8 warps = 2x4), 64 acc/thread.
__global__ __launch_bounds__(256, 2)
void gemm_bf16(const bf16* __restrict__ Ah, const bf16* __restrict__ Al, int lda, int Cin,
               const bf16* __restrict__ Wh, const bf16* __restrict__ Wl,
               float* __restrict__ C, int ldc) {
    __shared__ __align__(16) bf16 As[2][128 * 40];
    __shared__ __align__(16) bf16 Bs[2][128 * 40];
    int tid = threadIdx.x, lane = tid & 31, wid = tid >> 5;
    int warpM = wid >> 2, warpN = wid & 3;
    int jBase = blockIdx.x * 128;
    int nBase = blockIdx.y * 128;
    float acc[4][4][4];
    #pragma unroll
    for (int mt = 0; mt < 4; mt++)
        #pragma unroll
        for (int nt = 0; nt < 4; nt++)
            #pragma unroll
            for (int e = 0; e < 4; e++) acc[mt][nt][e] = 0.f;

    const int nIter = (3 * Cin) >> 5;
    const int ar = tid >> 1;
    const int ac = (tid & 1) * 2;      // 16B-chunk pair base
    uint4 pa0, pa1, pb0, pb1;

    gload(0, Cin, lda, Ah, Al, Wh, Wl, jBase, nBase, ar, ac, pa0, pa1, pb0, pb1);
    *(uint4*)(&As[0][ar * 40 + ac * 8])     = pa0;
    *(uint4*)(&As[0][ar * 40 + ac * 8 + 8]) = pa1;
    *(uint4*)(&Bs[0][ar * 40 + ac * 8])     = pb0;
    *(uint4*)(&Bs[0][ar * 40 + ac * 8 + 8]) = pb1;
    __syncthreads();

    for (int it = 0; it < nIter; it++) {
        int cur = it & 1;
        if (it + 1 < nIter)
            gload(it + 1, Cin, lda, Ah, Al, Wh, Wl, jBase, nBase, ar, ac,
                  pa0, pa1, pb0, pb1);

        uint32_t sA = smem_u32(&As[cur][0]);
        uint32_t sB = smem_u32(&Bs[cur][0]);
        #pragma unroll
        for (int s = 0; s < 2; s++) {
            uint32_t afr[4][4];
            uint32_t bfr[4][2];
            #pragma unroll
            for (int mt = 0; mt < 4; mt++) {
                uint32_t addrA = sA + ((warpM * 64 + mt * 16 + (lane & 15)) * 40) * 2
                               + s * 32 + ((lane >> 4) << 4);
                ldsm_x4(afr[mt][0], afr[mt][1], afr[mt][2], afr[mt][3], addrA);
            }
            #pragma unroll
            for (int nt = 0; nt < 4; nt++) {
                uint32_t addrB = sB + ((warpN * 32 + nt * 8 + (lane & 7)) * 40) * 2
                               + s * 32 + (((lane >> 3) & 1) << 4);
                ldsm_x2(bfr[nt][0], bfr[nt][1], addrB);
            }
            #pragma unroll
            for (int mt = 0; mt < 4; mt++)
                #pragma unroll
                for (int nt = 0; nt < 4; nt++)
                    mma16816(acc[mt][nt], afr[mt], bfr[nt]);
        }
        if (it + 1 < nIter) {
            int nxt = cur ^ 1;
            *(uint4*)(&As[nxt][ar * 40 + ac * 8])     = pa0;
            *(uint4*)(&As[nxt][ar * 40 + ac * 8 + 8]) = pa1;
            *(uint4*)(&Bs[nxt][ar * 40 + ac * 8])     = pb0;
            *(uint4*)(&Bs[nxt][ar * 40 + ac * 8 + 8]) = pb1;
        }
        __syncthreads();
    }

    #pragma unroll
    for (int mt = 0; mt < 4; mt++) {
        int m = jBase + warpM * 64 + mt * 16 + (lane >> 2);
        #pragma unroll
        for (int nt = 0; nt < 4; nt++) {
            int n = nBase + warpN * 32 + nt * 8 + (lane & 3) * 2;
            *(float2*)&C[(size_t)m * ldc + n]       = make_float2(acc[mt][nt][0], acc[mt][nt][1]);
            *(float2*)&C[(size_t)(m + 8) * ldc + n] = make_float2(acc[mt][nt][2], acc[mt][nt][3]);
        }
    }
}

// ---------------- vec_lna pointwise epilogue -> split dst ----------------
// C holds [U | Kr] (pitch 256). dst = s*u - min(dot,0)*k_dir, split to h/l.
__global__ void pointwise_kernel(const float* __restrict__ Cbuf,
                                 bf16* __restrict__ dstH, bf16* __restrict__ dstL,
                                 int ldd, int off) {
    __shared__ float sred[4];
    int bn = blockIdx.x;
    int c = threadIdx.x;
    int j0 = bn * 3;
    float ux = Cbuf[(size_t)(j0 + 0) * 256 + c];
    float uy = Cbuf[(size_t)(j0 + 1) * 256 + c];
    float uz = Cbuf[(size_t)(j0 + 2) * 256 + c];
    float kx = Cbuf[(size_t)(j0 + 0) * 256 + 128 + c];
    float ky = Cbuf[(size_t)(j0 + 1) * 256 + 128 + c];
    float kz = Cbuf[(size_t)(j0 + 2) * 256 + 128 + c];
    float tot = blockReduceSum128(ux * ux + uy * uy + uz * uz, sred);
    float s = 1.f / fmaxf(sqrtf(tot), EPSf);
    float kl = sqrtf(kx * kx + ky * ky + kz * kz);
    float ki = 1.f / fmaxf(kl, EPSf);
    kx *= ki; ky *= ki; kz *= ki;
    float dot = s * (ux * kx + uy * ky + uz * kz);
    float neg = fminf(dot, 0.f);
    split2(s * ux - neg * kx, dstH[(size_t)(j0 + 0) * ldd + off + c], dstL[(size_t)(j0 + 0) * ldd + off + c]);
    split2(s * uy - neg * ky, dstH[(size_t)(j0 + 1) * ldd + off + c], dstL[(size_t)(j0 + 1) * ldd + off + c]);
    split2(s * uz - neg * kz, dstH[(size_t)(j0 + 2) * ldd + off + c], dstL[(size_t)(j0 + 2) * ldd + off + c]);
}

// ---------------- mean over N of h1 (cols 0..127 of X2) ----------------
__global__ void meanN_kernel() {
    int bd = blockIdx.x;                    // b*3+d
    int b = bd / 3, d = bd % 3;
    int c = threadIdx.x;
    size_t base = ((size_t)(b * Npts) * 3 + d) * 256 + c;
    float s = 0.f;
    #pragma unroll 8
    for (int n = 0; n < Npts; n++) {
        size_t a = base + (size_t)n * 3 * 256;
        s += __bfloat162float(g_X2h[a]) + __bfloat162float(g_X2l[a]);
    }
    g_gmean[bd * Hc + c] = s;
}

// broadcast mean into cols 128..255 of X2 (split)
__global__ void bcast_kernel() {
    int t = blockIdx.x * blockDim.x + threadIdx.x;
    int c = t & 127;
    int j = t >> 7;
    int b = j / (Npts * 3);
    int d = j % 3;
    float v = g_gmean[(b * 3 + d) * Hc + c] * (1.f / (float)Npts);
    split2(v, g_X2h[(size_t)j * 256 + 128 + c], g_X2l[(size_t)j * 256 + 128 + c]);
}

// ---------------- final transpose write ----------------
__global__ void writeout_kernel(float* __restrict__ out, int big_off) {
    long long t = (long long)blockIdx.x * blockDim.x + threadIdx.x;
    int n = (int)(t & 2047);
    long long r = t >> 11;
    int d = (int)(r % 3); r /= 3;
    int o = (int)(r & 127);
    int b = (int)(r >> 7);
    out[big_off + t] = g_C[(((size_t)(b * Npts + n)) * 3 + d) * 128 + o];
}

__global__ void meanout_kernel(float* __restrict__ out, int big_off, int mean_off) {
    int w = blockIdx.x * 8 + (threadIdx.x >> 5);
    int lane = threadIdx.x & 31;
    const float* base = out + big_off + (size_t)w * Npts;
    float s = 0.f;
    #pragma unroll 8
    for (int i = lane; i < Npts; i += 32) s += base[i];
    #pragma unroll
    for (int o = 16; o > 0; o >>= 1) s += __shfl_xor_sync(0xffffffffu, s, o);
    if (lane == 0) out[mean_off + w] = s * (1.f / (float)Npts);
}

// ---------------- host launcher ----------------
extern "C" void kernel_launch(void* const* d_in, const int* in_sizes, int n_in,
                              void* d_out, int out_size) {
    const float* x     = (const float*)d_in[0];
    const float* W_in  = (const float*)d_in[1];
    const float* Wd_in = (const float*)d_in[2];
    const float* Ws    = (const float*)d_in[3];
    const float* Wds   = (const float*)d_in[4];
    const float* Gs    = (const float*)d_in[5];
    const float* Gds   = (const float*)d_in[6];
    const float* W_out = (const float*)d_in[7];
    float* out = (float*)d_out;

    float *pC;
    bf16 *pX0h, *pX0l, *pX2h, *pX2l, *pFTh, *pFTl, *pUKh, *pUKl, *pGWh, *pGWl, *pOWh, *pOWl;
    cudaGetSymbolAddress((void**)&pC, g_C);
    cudaGetSymbolAddress((void**)&pX0h, g_X0h);
    cudaGetSymbolAddress((void**)&pX0l, g_X0l);
    cudaGetSymbolAddress((void**)&pX2h, g_X2h);
    cudaGetSymbolAddress((void**)&pX2l, g_X2l);
    cudaGetSymbolAddress((void**)&pFTh, g_FTh);
    cudaGetSymbolAddress((void**)&pFTl, g_FTl);
    cudaGetSymbolAddress((void**)&pUKh, g_UKh);
    cudaGetSymbolAddress((void**)&pUKl, g_UKl);
    cudaGetSymbolAddress((void**)&pGWh, g_GWh);
    cudaGetSymbolAddress((void**)&pGWl, g_GWl);
    cudaGetSymbolAddress((void**)&pOWh, g_OWh);
    cudaGetSymbolAddress((void**)&pOWl, g_OWl);

    int mean_off = 0, big_off = 0;
    bool has_mean = true;
    const int BIG = Bsz * CDc * 3 * Npts;       // 6291456
    const int MEAN = Bsz * CDc * 3;             // 3072
    if (out_size >= BIG + MEAN) { mean_off = 0; big_off = MEAN; }
    else { big_off = 0; has_mean = false; }

    const int prepTot = 384 + Lc * 256 * 128 + Lc * 256 * 256 + 128 * 512;
    prep_kernel<<<(prepTot + 255) / 256, 256>>>(W_in, Wd_in, Ws, Wds, Gs, Gds, W_out);
    knn_kernel<<<Bsz * 8, 256>>>(x);
    stage2_kernel<<<NBlk, 128>>>(x, W_in);

    const bf16* Xh = pX0h;
    const bf16* Xl = pX0l;
    int lda = Hc;
    dim3 g2(Jtot / 128, 2), g1(Jtot / 128, 1);
    for (int i = 0; i < Lc; i++) {
        gemm_bf16<<<g2, 256>>>(Xh, Xl, lda, 128,
                               pUKh + (size_t)i * 256 * 128, pUKl + (size_t)i * 256 * 128,
                               pC, 256);
        pointwise_kernel<<<NBlk, 128>>>(pC, pX2h, pX2l, 256, 0);
        meanN_kernel<<<Bsz * 3, 128>>>();
        bcast_kernel<<<(Jtot * Hc) / 256, 256>>>();
        gemm_bf16<<<g2, 256>>>(pX2h, pX2l, 256, 256,
                               pGWh + (size_t)i * 256 * 256, pGWl + (size_t)i * 256 * 256,
                               pC, 256);
        pointwise_kernel<<<NBlk, 128>>>(pC, pFTh, pFTl, 512, i * 128);
        Xh = pFTh + (size_t)i * 128;
        Xl = pFTl + (size_t)i * 128;
        lda = 512;
    }
    // final projection: OUT = FEATS (J x 512) @ W_out^T (128 x 512)
    gemm_bf16<<<g1, 256>>>(pFTh, pFTl, 512, 512, pOWh, pOWl, pC, 128);
    writeout_kernel<<<(Jtot * Hc) / 256, 256>>>(out, big_off);
    if (has_mean) meanout_kernel<<<384, 256>>>(out, big_off, mean_off);
}

// round 6
// speedup vs baseline: 1.7794x; 1.2920x over previous
#include <cuda_runtime.h>
#include <cuda_bf16.h>
#include <math.h>
#include <float.h>
#include <stdint.h>

// ---------------- problem constants ----------------
#define Bsz   8
#define Npts  2048
#define Kn    16
#define Hc    128
#define Lc    4
#define CDc   128
#define Jtot  (Bsz * Npts * 3)
#define NBlk  (Bsz * Npts)
#define EPSf  1e-12f

typedef __nv_bfloat16 bf16;

// ---------------- scratch ----------------
__device__ int   g_idx[NBlk * Kn];
__device__ float g_M3[Hc * 3];
__device__ bf16  g_UKh[Lc * 256 * 128];
__device__ bf16  g_UKl[Lc * 256 * 128];
__device__ bf16  g_GWh[Lc * 256 * 256];
__device__ bf16  g_GWl[Lc * 256 * 256];
__device__ bf16  g_OWh[128 * 512];
__device__ bf16  g_OWl[128 * 512];
__device__ bf16  g_X0h[Jtot * 128];
__device__ bf16  g_X0l[Jtot * 128];
__device__ bf16  g_X2h[Jtot * 256];
__device__ bf16  g_X2l[Jtot * 256];
__device__ bf16  g_FTh[Jtot * 512];
__device__ bf16  g_FTl[Jtot * 512];
__device__ float g_C[Jtot * 256];
__device__ float g_gmean[Bsz * 3 * Hc];
__device__ float g_part[24 * 16 * Hc];

// ---------------- helpers ----------------
__device__ __forceinline__ void split2(float v, bf16& h, bf16& l) {
    h = __float2bfloat16(v);
    l = __float2bfloat16(v - __bfloat162float(h));
}

__device__ __forceinline__ uint32_t smem_u32(const void* p) {
    uint32_t r;
    asm("{ .reg .u64 t; cvta.to.shared.u64 t, %1; cvt.u32.u64 %0, t; }"
        : "=r"(r) : "l"(p));
    return r;
}

__device__ __forceinline__ void cpasync16(uint32_t dst, const void* src) {
    asm volatile("cp.async.cg.shared.global [%0], [%1], 16;" :: "r"(dst), "l"(src));
}
__device__ __forceinline__ void cpcommit() {
    asm volatile("cp.async.commit_group;" ::: "memory");
}
template <int N> __device__ __forceinline__ void cpwait() {
    asm volatile("cp.async.wait_group %0;" :: "n"(N) : "memory");
}

__device__ __forceinline__ void ldsm_x4(uint32_t& r0, uint32_t& r1,
                                        uint32_t& r2, uint32_t& r3, uint32_t addr) {
    asm volatile("ldmatrix.sync.aligned.m8n8.x4.shared.b16 {%0,%1,%2,%3}, [%4];"
                 : "=r"(r0), "=r"(r1), "=r"(r2), "=r"(r3) : "r"(addr));
}
__device__ __forceinline__ void ldsm_x2(uint32_t& r0, uint32_t& r1, uint32_t addr) {
    asm volatile("ldmatrix.sync.aligned.m8n8.x2.shared.b16 {%0,%1}, [%2];"
                 : "=r"(r0), "=r"(r1) : "r"(addr));
}
__device__ __forceinline__ void mma16816(float* d, const uint32_t* a, const uint32_t* b) {
    asm volatile("mma.sync.aligned.m16n8k16.row.col.f32.bf16.bf16.f32 "
                 "{%0,%1,%2,%3}, {%4,%5,%6,%7}, {%8,%9}, {%0,%1,%2,%3};"
                 : "+f"(d[0]), "+f"(d[1]), "+f"(d[2]), "+f"(d[3])
                 : "r"(a[0]), "r"(a[1]), "r"(a[2]), "r"(a[3]),
                   "r"(b[0]), "r"(b[1]));
}

// ---------------- prep: fused+stacked+split weights ----------------
__global__ void prep_kernel(const float* __restrict__ W_in,
                            const float* __restrict__ Wd_in,
                            const float* __restrict__ Ws,
                            const float* __restrict__ Wds,
                            const float* __restrict__ Gs,
                            const float* __restrict__ Gds,
                            const float* __restrict__ W_out) {
    int t = blockIdx.x * blockDim.x + threadIdx.x;
    const int N3  = Hc * 3;
    const int NUK = Lc * 256 * 128;
    const int NGW = Lc * 256 * 256;
    const int NOW = 128 * 512;
    if (t < N3) {
        int o = t / 3, i = t % 3;
        float s = 0.f;
        #pragma unroll 8
        for (int c = 0; c < Hc; c++) s += Wd_in[o * Hc + c] * W_in[c * 3 + i];
        g_M3[t] = s;
    } else if (t < N3 + NUK) {
        int r = t - N3;
        int l = r >> 15;
        int o = (r >> 7) & 255;
        int c = r & 127;
        float v;
        if (o < 128) {
            v = Ws[l * Hc * Hc + o * Hc + c];
        } else {
            const float* wd = Wds + l * Hc * Hc + (o - 128) * Hc;
            const float* w  = Ws  + l * Hc * Hc;
            float s = 0.f;
            #pragma unroll 8
            for (int cc = 0; cc < Hc; cc++) s += wd[cc] * w[cc * Hc + c];
            v = s;
        }
        split2(v, g_UKh[r], g_UKl[r]);
    } else if (t < N3 + NUK + NGW) {
        int r = t - N3 - NUK;
        int l = r >> 16;
        int o = (r >> 8) & 255;
        int c = r & 255;
        float v;
        if (o < 128) {
            v = Gs[l * Hc * 2 * Hc + o * 2 * Hc + c];
        } else {
            const float* gd = Gds + l * Hc * Hc + (o - 128) * Hc;
            const float* g  = Gs  + l * Hc * 2 * Hc;
            float s = 0.f;
            #pragma unroll 8
            for (int cc = 0; cc < Hc; cc++) s += gd[cc] * g[cc * 2 * Hc + c];
            v = s;
        }
        split2(v, g_GWh[r], g_GWl[r]);
    } else if (t < N3 + NUK + NGW + NOW) {
        int r = t - N3 - NUK - NGW;
        split2(W_out[r], g_OWh[r], g_OWl[r]);
    }
}

// ---------------- kNN ----------------
__global__ void knn_kernel(const float* __restrict__ x) {
    __shared__ float4 spts[Npts];
    int b = blockIdx.x >> 3;
    int chunk = blockIdx.x & 7;
    const float* xb = x + b * 3 * Npts;
    for (int i = threadIdx.x; i < Npts; i += 256) {
        float px = xb[i], py = xb[Npts + i], pz = xb[2 * Npts + i];
        spts[i] = make_float4(px, py, pz, px * px + py * py + pz * pz);
    }
    __syncthreads();
    int q = chunk * 256 + threadIdx.x;
    float4 Q = spts[q];
    float bd[Kn]; int bi[Kn];
    #pragma unroll
    for (int t = 0; t < Kn; t++) { bd[t] = FLT_MAX; bi[t] = 0; }
    float worst = FLT_MAX; int wslot = 0;
    for (int m = 0; m < Npts; m++) {
        float4 P = spts[m];
        float d2 = Q.w + P.w - 2.f * (Q.x * P.x + Q.y * P.y + Q.z * P.z);
        if (d2 < worst) {
            #pragma unroll
            for (int t = 0; t < Kn; t++) if (t == wslot) { bd[t] = d2; bi[t] = m; }
            worst = bd[0]; wslot = 0;
            #pragma unroll
            for (int t = 1; t < Kn; t++) if (bd[t] > worst) { worst = bd[t]; wslot = t; }
        }
    }
    int base = (b * Npts + q) * Kn;
    #pragma unroll
    for (int t = 0; t < Kn; t++) g_idx[base + t] = bi[t];
}

// ---------------- fused edge stage (batched reductions, 2 syncs) ----------------
__global__ void stage2_kernel(const float* __restrict__ x,
                              const float* __restrict__ W_in) {
    __shared__ float3 snbr[Kn];
    __shared__ float swk[4][Kn];
    int bn = blockIdx.x;
    int b = bn >> 11, n = bn & 2047;
    int c = threadIdx.x;
    int wid = c >> 5, lane = c & 31;
    const float* xb = x + b * 3 * Npts;
    float xnx = xb[n], xny = xb[Npts + n], xnz = xb[2 * Npts + n];
    float xl = sqrtf(xnx * xnx + xny * xny + xnz * xnz);
    float xinv = 1.f / fmaxf(xl, EPSf);
    float dxx = xnx * xinv, dxy = xny * xinv, dxz = xnz * xinv;
    if (c < Kn) {
        int m = g_idx[bn * Kn + c];
        snbr[c] = make_float3(xb[m], xb[Npts + m], xb[2 * Npts + m]);
    }
    __syncthreads();
    float w0 = W_in[c * 3 + 0], w1 = W_in[c * 3 + 1], w2 = W_in[c * 3 + 2];
    float m0 = g_M3[c * 3 + 0], m1 = g_M3[c * 3 + 1], m2 = g_M3[c * 3 + 2];
    float sumk[Kn];
    #pragma unroll
    for (int k = 0; k < Kn; k++) {
        float3 p = snbr[k];
        float c0x = dxy * p.z - dxz * p.y;
        float c0y = dxz * p.x - dxx * p.z;
        float c0z = dxx * p.y - dxy * p.x;
        float e1x = p.x - xnx, e1y = p.y - xny, e1z = p.z - xnz;
        float ux = w0 * c0x + w1 * e1x + w2 * xnx;
        float uy = w0 * c0y + w1 * e1y + w2 * xny;
        float uz = w0 * c0z + w1 * e1z + w2 * xnz;
        sumk[k] = ux * ux + uy * uy + uz * uz;
    }
    #pragma unroll
    for (int o = 16; o > 0; o >>= 1)
        #pragma unroll
        for (int k = 0; k < Kn; k++)
            sumk[k] += __shfl_xor_sync(0xffffffffu, sumk[k], o);
    if (lane == 0) {
        #pragma unroll
        for (int k = 0; k < Kn; k++) swk[wid][k] = sumk[k];
    }
    __syncthreads();
    float ax = 0.f, ay = 0.f, az = 0.f;
    #pragma unroll
    for (int k = 0; k < Kn; k++) {
        float tot = swk[0][k] + swk[1][k] + swk[2][k] + swk[3][k];
        float3 p = snbr[k];
        float c0x = dxy * p.z - dxz * p.y;
        float c0y = dxz * p.x - dxx * p.z;
        float c0z = dxx * p.y - dxy * p.x;
        float e1x = p.x - xnx, e1y = p.y - xny, e1z = p.z - xnz;
        float ux = w0 * c0x + w1 * e1x + w2 * xnx;
        float uy = w0 * c0y + w1 * e1y + w2 * xny;
        float uz = w0 * c0z + w1 * e1z + w2 * xnz;
        float kx = m0 * c0x + m1 * e1x + m2 * xnx;
        float ky = m0 * c0y + m1 * e1y + m2 * xny;
        float kz = m0 * c0z + m1 * e1z + m2 * xnz;
        float s = 1.f / fmaxf(sqrtf(tot), EPSf);
        float kl = sqrtf(kx * kx + ky * ky + kz * kz);
        float ki = 1.f / fmaxf(kl, EPSf);
        kx *= ki; ky *= ki; kz *= ki;
        float dot = s * (ux * kx + uy * ky + uz * kz);
        float neg = fminf(dot, 0.f);
        ax += s * ux - neg * kx;
        ay += s * uy - neg * ky;
        az += s * uz - neg * kz;
    }
    const float invK = 1.f / (float)Kn;
    int j0 = bn * 3;
    split2(ax * invK, g_X0h[(size_t)(j0 + 0) * Hc + c], g_X0l[(size_t)(j0 + 0) * Hc + c]);
    split2(ay * invK, g_X0h[(size_t)(j0 + 1) * Hc + c], g_X0l[(size_t)(j0 + 1) * Hc + c]);
    split2(az * invK, g_X0h[(size_t)(j0 + 2) * Hc + c], g_X0l[(size_t)(j0 + 2) * Hc + c]);
}

// ---------------- bf16x3 mma.sync GEMM with cp.async double buffer ----------------
// C[j][n] = sum_c A[j,c]*W[n,c]; extended K' = 3*Cin: (Ah,Wh),(Al,Wh),(Ah,Wl).
// BM=128, BN=128, BK=32, 256 threads (8 warps = 2x4), 64 acc/thread.
__global__ __launch_bounds__(256, 2)
void gemm_bf16(const bf16* __restrict__ Ah, const bf16* __restrict__ Al, int lda, int Cin,
               const bf16* __restrict__ Wh, const bf16* __restrict__ Wl,
               float* __restrict__ C, int ldc) {
    __shared__ __align__(16) bf16 As[2][128 * 40];
    __shared__ __align__(16) bf16 Bs[2][128 * 40];
    int tid = threadIdx.x, lane = tid & 31, wid = tid >> 5;
    int warpM = wid >> 2, warpN = wid & 3;
    int jBase = blockIdx.x * 128;
    int nBase = blockIdx.y * 128;
    float acc[4][4][4];
    #pragma unroll
    for (int mt = 0; mt < 4; mt++)
        #pragma unroll
        for (int nt = 0; nt < 4; nt++)
            #pragma unroll
            for (int e = 0; e < 4; e++) acc[mt][nt][e] = 0.f;

    const int nIter = (3 * Cin) >> 5;
    // each thread copies 2 A-chunks + 2 B-chunks of 16B per slab
    const int ar = tid >> 1;
    const int ac = (tid & 1) * 2;              // chunk index {0,2}
    uint32_t sA0 = smem_u32(&As[0][0]);
    uint32_t sB0 = smem_u32(&Bs[0][0]);

    // cp.async slab loader into buffer BUF for extended-K iteration IT
    #define LOAD_SLAB(IT, BUF)                                                     \
    do {                                                                           \
        int k0 = (IT) << 5;                                                        \
        int seg = k0 / Cin;                                                        \
        int kin = k0 - seg * Cin;                                                  \
        const bf16* Ap = (seg == 1) ? Al : Ah;                                     \
        const bf16* Bp = (seg == 2) ? Wl : Wh;                                     \
        uint32_t adst = sA0 + (BUF) * 10240 + (ar * 40 + ac * 8) * 2;              \
        uint32_t bdst = sB0 + (BUF) * 10240 + (ar * 40 + ac * 8) * 2;              \
        cpasync16(adst,      Ap + (size_t)(jBase + ar) * lda + kin + ac * 8);      \
        cpasync16(adst + 16, Ap + (size_t)(jBase + ar) * lda + kin + ac * 8 + 8);  \
        cpasync16(bdst,      Bp + (size_t)(nBase + ar) * Cin + kin + ac * 8);      \
        cpasync16(bdst + 16, Bp + (size_t)(nBase + ar) * Cin + kin + ac * 8 + 8);  \
    } while (0)

    LOAD_SLAB(0, 0);
    cpcommit();
    cpwait<0>();
    __syncthreads();

    for (int it = 0; it < nIter; it++) {
        int cur = it & 1;
        if (it + 1 < nIter) {
            LOAD_SLAB(it + 1, cur ^ 1);
            cpcommit();
        }
        uint32_t sA = sA0 + cur * 10240;
        uint32_t sB = sB0 + cur * 10240;
        #pragma unroll
        for (int s = 0; s < 2; s++) {
            uint32_t afr[4][4];
            uint32_t bfr[4][2];
            #pragma unroll
            for (int mt = 0; mt < 4; mt++) {
                uint32_t addrA = sA + ((warpM * 64 + mt * 16 + (lane & 15)) * 40) * 2
                               + s * 32 + ((lane >> 4) << 4);
                ldsm_x4(afr[mt][0], afr[mt][1], afr[mt][2], afr[mt][3], addrA);
            }
            #pragma unroll
            for (int nt = 0; nt < 4; nt++) {
                uint32_t addrB = sB + ((warpN * 32 + nt * 8 + (lane & 7)) * 40) * 2
                               + s * 32 + (((lane >> 3) & 1) << 4);
                ldsm_x2(bfr[nt][0], bfr[nt][1], addrB);
            }
            #pragma unroll
            for (int mt = 0; mt < 4; mt++)
                #pragma unroll
                for (int nt = 0; nt < 4; nt++)
                    mma16816(acc[mt][nt], afr[mt], bfr[nt]);
        }
        if (it + 1 < nIter) {
            cpwait<0>();
            __syncthreads();
        }
    }
    #undef LOAD_SLAB

    #pragma unroll
    for (int mt = 0; mt < 4; mt++) {
        int m = jBase + warpM * 64 + mt * 16 + (lane >> 2);
        #pragma unroll
        for (int nt = 0; nt < 4; nt++) {
            int n = nBase + warpN * 32 + nt * 8 + (lane & 3) * 2;
            *(float2*)&C[(size_t)m * ldc + n]       = make_float2(acc[mt][nt][0], acc[mt][nt][1]);
            *(float2*)&C[(size_t)(m + 8) * ldc + n] = make_float2(acc[mt][nt][2], acc[mt][nt][3]);
        }
    }
}

// ---------------- vec_lna pointwise epilogue (2 bn per block) ----------------
__global__ __launch_bounds__(256)
void pointwise_kernel(const float* __restrict__ Cbuf,
                      bf16* __restrict__ dstH, bf16* __restrict__ dstL,
                      int ldd, int off) {
    __shared__ float sred[2][4];
    int half = threadIdx.x >> 7;
    int c = threadIdx.x & 127;
    int wih = (threadIdx.x >> 5) & 3;
    int lane = threadIdx.x & 31;
    int bn = blockIdx.x * 2 + half;
    int j0 = bn * 3;
    float ux = Cbuf[(size_t)(j0 + 0) * 256 + c];
    float uy = Cbuf[(size_t)(j0 + 1) * 256 + c];
    float uz = Cbuf[(size_t)(j0 + 2) * 256 + c];
    float kx = Cbuf[(size_t)(j0 + 0) * 256 + 128 + c];
    float ky = Cbuf[(size_t)(j0 + 1) * 256 + 128 + c];
    float kz = Cbuf[(size_t)(j0 + 2) * 256 + 128 + c];
    float v = ux * ux + uy * uy + uz * uz;
    #pragma unroll
    for (int o = 16; o > 0; o >>= 1) v += __shfl_xor_sync(0xffffffffu, v, o);
    if (lane == 0) sred[half][wih] = v;
    __syncthreads();
    float tot = sred[half][0] + sred[half][1] + sred[half][2] + sred[half][3];
    float s = 1.f / fmaxf(sqrtf(tot), EPSf);
    float kl = sqrtf(kx * kx + ky * ky + kz * kz);
    float ki = 1.f / fmaxf(kl, EPSf);
    kx *= ki; ky *= ki; kz *= ki;
    float dot = s * (ux * kx + uy * ky + uz * kz);
    float neg = fminf(dot, 0.f);
    split2(s * ux - neg * kx, dstH[(size_t)(j0 + 0) * ldd + off + c], dstL[(size_t)(j0 + 0) * ldd + off + c]);
    split2(s * uy - neg * ky, dstH[(size_t)(j0 + 1) * ldd + off + c], dstL[(size_t)(j0 + 1) * ldd + off + c]);
    split2(s * uz - neg * kz, dstH[(size_t)(j0 + 2) * ldd + off + c], dstL[(size_t)(j0 + 2) * ldd + off + c]);
}

// ---------------- two-stage mean over N ----------------
__global__ void meanN_part() {
    int bd = blockIdx.x;
    int slab = blockIdx.y;
    int b = bd / 3, d = bd % 3;
    int c = threadIdx.x;
    size_t base = ((size_t)(b * Npts + slab * 128) * 3 + d) * 256 + c;
    float s = 0.f;
    #pragma unroll 8
    for (int n = 0; n < 128; n++) {
        size_t a = base + (size_t)n * 3 * 256;
        s += __bfloat162float(g_X2h[a]) + __bfloat162float(g_X2l[a]);
    }
    g_part[(bd * 16 + slab) * Hc + c] = s;
}

__global__ void meanN_reduce() {
    int bd = blockIdx.x;
    int c = threadIdx.x;
    float s = 0.f;
    #pragma unroll
    for (int p = 0; p < 16; p++) s += g_part[(bd * 16 + p) * Hc + c];
    g_gmean[bd * Hc + c] = s;
}

__global__ void bcast_kernel() {
    int t = blockIdx.x * blockDim.x + threadIdx.x;
    int c = t & 127;
    int j = t >> 7;
    int b = j / (Npts * 3);
    int d = j % 3;
    float v = g_gmean[(b * 3 + d) * Hc + c] * (1.f / (float)Npts);
    split2(v, g_X2h[(size_t)j * 256 + 128 + c], g_X2l[(size_t)j * 256 + 128 + c]);
}

// ---------------- coalesced tiled-transpose writeout ----------------
// g_C: [(b,n,d)][o] (pitch 128). out big: [(b,o,d)][n].
// grid: (n/32, o/32, b*3+d). block 256 = 32x8.
__global__ __launch_bounds__(256)
void writeout_kernel(float* __restrict__ out, int big_off) {
    __shared__ float tile[32][33];
    int tx = threadIdx.x & 31;
    int ty = threadIdx.x >> 5;           // 0..7
    int n0 = blockIdx.x * 32;
    int o0 = blockIdx.y * 32;
    int bd = blockIdx.z;
    int b = bd / 3, d = bd % 3;
    #pragma unroll
    for (int i = 0; i < 4; i++) {
        int n = n0 + ty + i * 8;
        tile[ty + i * 8][tx] = g_C[(((size_t)(b * Npts + n)) * 3 + d) * 128 + o0 + tx];
    }
    __syncthreads();
    #pragma unroll
    for (int i = 0; i < 4; i++) {
        int o = o0 + ty + i * 8;
        out[big_off + (((size_t)(b * 128 + o)) * 3 + d) * Npts + n0 + tx] = tile[tx][ty + i * 8];
    }
}

__global__ void meanout_kernel(float* __restrict__ out, int big_off, int mean_off) {
    int w = blockIdx.x * 8 + (threadIdx.x >> 5);
    int lane = threadIdx.x & 31;
    const float* base = out + big_off + (size_t)w * Npts;
    float s = 0.f;
    #pragma unroll 8
    for (int i = lane; i < Npts; i += 32) s += base[i];
    #pragma unroll
    for (int o = 16; o > 0; o >>= 1) s += __shfl_xor_sync(0xffffffffu, s, o);
    if (lane == 0) out[mean_off + w] = s * (1.f / (float)Npts);
}

// ---------------- host launcher ----------------
extern "C" void kernel_launch(void* const* d_in, const int* in_sizes, int n_in,
                              void* d_out, int out_size) {
    const float* x     = (const float*)d_in[0];
    const float* W_in  = (const float*)d_in[1];
    const float* Wd_in = (const float*)d_in[2];
    const float* Ws    = (const float*)d_in[3];
    const float* Wds   = (const float*)d_in[4];
    const float* Gs    = (const float*)d_in[5];
    const float* Gds   = (const float*)d_in[6];
    const float* W_out = (const float*)d_in[7];
    float* out = (float*)d_out;

    float *pC;
    bf16 *pX0h, *pX0l, *pX2h, *pX2l, *pFTh, *pFTl, *pUKh, *pUKl, *pGWh, *pGWl, *pOWh, *pOWl;
    cudaGetSymbolAddress((void**)&pC, g_C);
    cudaGetSymbolAddress((void**)&pX0h, g_X0h);
    cudaGetSymbolAddress((void**)&pX0l, g_X0l);
    cudaGetSymbolAddress((void**)&pX2h, g_X2h);
    cudaGetSymbolAddress((void**)&pX2l, g_X2l);
    cudaGetSymbolAddress((void**)&pFTh, g_FTh);
    cudaGetSymbolAddress((void**)&pFTl, g_FTl);
    cudaGetSymbolAddress((void**)&pUKh, g_UKh);
    cudaGetSymbolAddress((void**)&pUKl, g_UKl);
    cudaGetSymbolAddress((void**)&pGWh, g_GWh);
    cudaGetSymbolAddress((void**)&pGWl, g_GWl);
    cudaGetSymbolAddress((void**)&pOWh, g_OWh);
    cudaGetSymbolAddress((void**)&pOWl, g_OWl);

    int mean_off = 0, big_off = 0;
    bool has_mean = true;
    const int BIG = Bsz * CDc * 3 * Npts;
    const int MEAN = Bsz * CDc * 3;
    if (out_size >= BIG + MEAN) { mean_off = 0; big_off = MEAN; }
    else { big_off = 0; has_mean = false; }

    const int prepTot = 384 + Lc * 256 * 128 + Lc * 256 * 256 + 128 * 512;
    prep_kernel<<<(prepTot + 255) / 256, 256>>>(W_in, Wd_in, Ws, Wds, Gs, Gds, W_out);
    knn_kernel<<<Bsz * 8, 256>>>(x);
    stage2_kernel<<<NBlk, 128>>>(x, W_in);

    const bf16* Xh = pX0h;
    const bf16* Xl = pX0l;
    int lda = Hc;
    dim3 g2(Jtot / 128, 2), g1(Jtot / 128, 1);
    for (int i = 0; i < Lc; i++) {
        gemm_bf16<<<g2, 256>>>(Xh, Xl, lda, 128,
                               pUKh + (size_t)i * 256 * 128, pUKl + (size_t)i * 256 * 128,
                               pC, 256);
        pointwise_kernel<<<NBlk / 2, 256>>>(pC, pX2h, pX2l, 256, 0);
        meanN_part<<<dim3(24, 16), 128>>>();
        meanN_reduce<<<24, 128>>>();
        bcast_kernel<<<(Jtot * Hc) / 256, 256>>>();
        gemm_bf16<<<g2, 256>>>(pX2h, pX2l, 256, 256,
                               pGWh + (size_t)i * 256 * 256, pGWl + (size_t)i * 256 * 256,
                               pC, 256);
        pointwise_kernel<<<NBlk / 2, 256>>>(pC, pFTh, pFTl, 512, i * 128);
        Xh = pFTh + (size_t)i * 128;
        Xl = pFTl + (size_t)i * 128;
        lda = 512;
    }
    gemm_bf16<<<g1, 256>>>(pFTh, pFTl, 512, 512, pOWh, pOWl, pC, 128);
    writeout_kernel<<<dim3(Npts / 32, 4, 24), 256>>>(out, big_off);
    if (has_mean) meanout_kernel<<<384, 256>>>(out, big_off, mean_off);
}

// round 7
// speedup vs baseline: 1.8339x; 1.0306x over previous
#include <cuda_runtime.h>
#include <cuda_bf16.h>
#include <math.h>
#include <float.h>
#include <stdint.h>

// ---------------- problem constants ----------------
#define Bsz   8
#define Npts  2048
#define Kn    16
#define Hc    128
#define Lc    4
#define CDc   128
#define Jtot  (Bsz * Npts * 3)
#define NBlk  (Bsz * Npts)
#define EPSf  1e-12f

typedef __nv_bfloat16 bf16;

// ---------------- scratch ----------------
__device__ int   g_idx[NBlk * Kn];
__device__ float g_M3[Hc * 3];
__device__ bf16  g_UKh[Lc * 256 * 128];
__device__ bf16  g_UKl[Lc * 256 * 128];
__device__ bf16  g_GWh[Lc * 256 * 256];
__device__ bf16  g_GWl[Lc * 256 * 256];
__device__ bf16  g_OWh[128 * 512];
__device__ bf16  g_OWl[128 * 512];
__device__ bf16  g_X0h[Jtot * 128];
__device__ bf16  g_X0l[Jtot * 128];
__device__ bf16  g_X2h[Jtot * 128];          // h1 only (pitch 128) — g-half eliminated
__device__ bf16  g_X2l[Jtot * 128];
__device__ bf16  g_FTh[Jtot * 512];
__device__ bf16  g_FTl[Jtot * 512];
__device__ float g_C[Jtot * 256];
__device__ float g_gmean[Bsz * 3 * Hc];      // raw sum over N of h1
__device__ float g_bias[24 * 256];           // per-(b,d) [U|Kr] bias from g-half

// ---------------- helpers ----------------
__device__ __forceinline__ void split2(float v, bf16& h, bf16& l) {
    h = __float2bfloat16(v);
    l = __float2bfloat16(v - __bfloat162float(h));
}

__device__ __forceinline__ uint32_t smem_u32(const void* p) {
    uint32_t r;
    asm("{ .reg .u64 t; cvta.to.shared.u64 t, %1; cvt.u32.u64 %0, t; }"
        : "=r"(r) : "l"(p));
    return r;
}

__device__ __forceinline__ void cpasync16(uint32_t dst, const void* src) {
    asm volatile("cp.async.cg.shared.global [%0], [%1], 16;" :: "r"(dst), "l"(src));
}
__device__ __forceinline__ void cpcommit() {
    asm volatile("cp.async.commit_group;" ::: "memory");
}
template <int N> __device__ __forceinline__ void cpwait() {
    asm volatile("cp.async.wait_group %0;" :: "n"(N) : "memory");
}

__device__ __forceinline__ void ldsm_x4(uint32_t& r0, uint32_t& r1,
                                        uint32_t& r2, uint32_t& r3, uint32_t addr) {
    asm volatile("ldmatrix.sync.aligned.m8n8.x4.shared.b16 {%0,%1,%2,%3}, [%4];"
                 : "=r"(r0), "=r"(r1), "=r"(r2), "=r"(r3) : "r"(addr));
}
__device__ __forceinline__ void ldsm_x2(uint32_t& r0, uint32_t& r1, uint32_t addr) {
    asm volatile("ldmatrix.sync.aligned.m8n8.x2.shared.b16 {%0,%1}, [%2];"
                 : "=r"(r0), "=r"(r1) : "r"(addr));
}
__device__ __forceinline__ void mma16816(float* d, const uint32_t* a, const uint32_t* b) {
    asm volatile("mma.sync.aligned.m16n8k16.row.col.f32.bf16.bf16.f32 "
                 "{%0,%1,%2,%3}, {%4,%5,%6,%7}, {%8,%9}, {%0,%1,%2,%3};"
                 : "+f"(d[0]), "+f"(d[1]), "+f"(d[2]), "+f"(d[3])
                 : "r"(a[0]), "r"(a[1]), "r"(a[2]), "r"(a[3]),
                   "r"(b[0]), "r"(b[1]));
}

// ---------------- prep: fused+stacked+split weights ----------------
__global__ void prep_kernel(const float* __restrict__ W_in,
                            const float* __restrict__ Wd_in,
                            const float* __restrict__ Ws,
                            const float* __restrict__ Wds,
                            const float* __restrict__ Gs,
                            const float* __restrict__ Gds,
                            const float* __restrict__ W_out) {
    int t = blockIdx.x * blockDim.x + threadIdx.x;
    const int N3  = Hc * 3;
    const int NUK = Lc * 256 * 128;
    const int NGW = Lc * 256 * 256;
    const int NOW = 128 * 512;
    if (t < N3) {
        int o = t / 3, i = t % 3;
        float s = 0.f;
        #pragma unroll 8
        for (int c = 0; c < Hc; c++) s += Wd_in[o * Hc + c] * W_in[c * 3 + i];
        g_M3[t] = s;
    } else if (t < N3 + NUK) {
        int r = t - N3;
        int l = r >> 15;
        int o = (r >> 7) & 255;
        int c = r & 127;
        float v;
        if (o < 128) {
            v = Ws[l * Hc * Hc + o * Hc + c];
        } else {
            const float* wd = Wds + l * Hc * Hc + (o - 128) * Hc;
            const float* w  = Ws  + l * Hc * Hc;
            float s = 0.f;
            #pragma unroll 8
            for (int cc = 0; cc < Hc; cc++) s += wd[cc] * w[cc * Hc + c];
            v = s;
        }
        split2(v, g_UKh[r], g_UKl[r]);
    } else if (t < N3 + NUK + NGW) {
        int r = t - N3 - NUK;
        int l = r >> 16;
        int o = (r >> 8) & 255;
        int c = r & 255;
        float v;
        if (o < 128) {
            v = Gs[l * Hc * 2 * Hc + o * 2 * Hc + c];
        } else {
            const float* gd = Gds + l * Hc * Hc + (o - 128) * Hc;
            const float* g  = Gs  + l * Hc * 2 * Hc;
            float s = 0.f;
            #pragma unroll 8
            for (int cc = 0; cc < Hc; cc++) s += gd[cc] * g[cc * 2 * Hc + c];
            v = s;
        }
        split2(v, g_GWh[r], g_GWl[r]);
    } else if (t < N3 + NUK + NGW + NOW) {
        int r = t - N3 - NUK - NGW;
        split2(W_out[r], g_OWh[r], g_OWl[r]);
    }
}

// ---------------- kNN ----------------
__global__ void knn_kernel(const float* __restrict__ x) {
    __shared__ float4 spts[Npts];
    int b = blockIdx.x >> 3;
    int chunk = blockIdx.x & 7;
    const float* xb = x + b * 3 * Npts;
    for (int i = threadIdx.x; i < Npts; i += 256) {
        float px = xb[i], py = xb[Npts + i], pz = xb[2 * Npts + i];
        spts[i] = make_float4(px, py, pz, px * px + py * py + pz * pz);
    }
    __syncthreads();
    int q = chunk * 256 + threadIdx.x;
    float4 Q = spts[q];
    float bd[Kn]; int bi[Kn];
    #pragma unroll
    for (int t = 0; t < Kn; t++) { bd[t] = FLT_MAX; bi[t] = 0; }
    float worst = FLT_MAX; int wslot = 0;
    for (int m = 0; m < Npts; m++) {
        float4 P = spts[m];
        float d2 = Q.w + P.w - 2.f * (Q.x * P.x + Q.y * P.y + Q.z * P.z);
        if (d2 < worst) {
            #pragma unroll
            for (int t = 0; t < Kn; t++) if (t == wslot) { bd[t] = d2; bi[t] = m; }
            worst = bd[0]; wslot = 0;
            #pragma unroll
            for (int t = 1; t < Kn; t++) if (bd[t] > worst) { worst = bd[t]; wslot = t; }
        }
    }
    int base = (b * Npts + q) * Kn;
    #pragma unroll
    for (int t = 0; t < Kn; t++) g_idx[base + t] = bi[t];
}

// ---------------- fused edge stage ----------------
__global__ void stage2_kernel(const float* __restrict__ x,
                              const float* __restrict__ W_in) {
    __shared__ float3 snbr[Kn];
    __shared__ float swk[4][Kn];
    int bn = blockIdx.x;
    int b = bn >> 11, n = bn & 2047;
    int c = threadIdx.x;
    int wid = c >> 5, lane = c & 31;
    const float* xb = x + b * 3 * Npts;
    float xnx = xb[n], xny = xb[Npts + n], xnz = xb[2 * Npts + n];
    float xl = sqrtf(xnx * xnx + xny * xny + xnz * xnz);
    float xinv = 1.f / fmaxf(xl, EPSf);
    float dxx = xnx * xinv, dxy = xny * xinv, dxz = xnz * xinv;
    if (c < Kn) {
        int m = g_idx[bn * Kn + c];
        snbr[c] = make_float3(xb[m], xb[Npts + m], xb[2 * Npts + m]);
    }
    __syncthreads();
    float w0 = W_in[c * 3 + 0], w1 = W_in[c * 3 + 1], w2 = W_in[c * 3 + 2];
    float m0 = g_M3[c * 3 + 0], m1 = g_M3[c * 3 + 1], m2 = g_M3[c * 3 + 2];
    float sumk[Kn];
    #pragma unroll
    for (int k = 0; k < Kn; k++) {
        float3 p = snbr[k];
        float c0x = dxy * p.z - dxz * p.y;
        float c0y = dxz * p.x - dxx * p.z;
        float c0z = dxx * p.y - dxy * p.x;
        float e1x = p.x - xnx, e1y = p.y - xny, e1z = p.z - xnz;
        float ux = w0 * c0x + w1 * e1x + w2 * xnx;
        float uy = w0 * c0y + w1 * e1y + w2 * xny;
        float uz = w0 * c0z + w1 * e1z + w2 * xnz;
        sumk[k] = ux * ux + uy * uy + uz * uz;
    }
    #pragma unroll
    for (int o = 16; o > 0; o >>= 1)
        #pragma unroll
        for (int k = 0; k < Kn; k++)
            sumk[k] += __shfl_xor_sync(0xffffffffu, sumk[k], o);
    if (lane == 0) {
        #pragma unroll
        for (int k = 0; k < Kn; k++) swk[wid][k] = sumk[k];
    }
    __syncthreads();
    float ax = 0.f, ay = 0.f, az = 0.f;
    #pragma unroll
    for (int k = 0; k < Kn; k++) {
        float tot = swk[0][k] + swk[1][k] + swk[2][k] + swk[3][k];
        float3 p = snbr[k];
        float c0x = dxy * p.z - dxz * p.y;
        float c0y = dxz * p.x - dxx * p.z;
        float c0z = dxx * p.y - dxy * p.x;
        float e1x = p.x - xnx, e1y = p.y - xny, e1z = p.z - xnz;
        float ux = w0 * c0x + w1 * e1x + w2 * xnx;
        float uy = w0 * c0y + w1 * e1y + w2 * xny;
        float uz = w0 * c0z + w1 * e1z + w2 * xnz;
        float kx = m0 * c0x + m1 * e1x + m2 * xnx;
        float ky = m0 * c0y + m1 * e1y + m2 * xny;
        float kz = m0 * c0z + m1 * e1z + m2 * xnz;
        float s = 1.f / fmaxf(sqrtf(tot), EPSf);
        float kl = sqrtf(kx * kx + ky * ky + kz * kz);
        float ki = 1.f / fmaxf(kl, EPSf);
        kx *= ki; ky *= ki; kz *= ki;
        float dot = s * (ux * kx + uy * ky + uz * kz);
        float neg = fminf(dot, 0.f);
        ax += s * ux - neg * kx;
        ay += s * uy - neg * ky;
        az += s * uz - neg * kz;
    }
    const float invK = 1.f / (float)Kn;
    int j0 = bn * 3;
    split2(ax * invK, g_X0h[(size_t)(j0 + 0) * Hc + c], g_X0l[(size_t)(j0 + 0) * Hc + c]);
    split2(ay * invK, g_X0h[(size_t)(j0 + 1) * Hc + c], g_X0l[(size_t)(j0 + 1) * Hc + c]);
    split2(az * invK, g_X0h[(size_t)(j0 + 2) * Hc + c], g_X0l[(size_t)(j0 + 2) * Hc + c]);
}

// ---------------- bf16x3 mma.sync GEMM (cp.async db) + optional row-group bias ----
// C[j][n] = sum_c A[j,c]*W[n,c] (+ bias[bd(j)*256+n]); K' = 3*Cin segments.
__global__ __launch_bounds__(256, 2)
void gemm_bf16(const bf16* __restrict__ Ah, const bf16* __restrict__ Al, int lda, int Cin,
               const bf16* __restrict__ Wh, const bf16* __restrict__ Wl, int ldw,
               float* __restrict__ C, int ldc, const float* __restrict__ bias) {
    __shared__ __align__(16) bf16 As[2][128 * 40];
    __shared__ __align__(16) bf16 Bs[2][128 * 40];
    int tid = threadIdx.x, lane = tid & 31, wid = tid >> 5;
    int warpM = wid >> 2, warpN = wid & 3;
    int jBase = blockIdx.x * 128;
    int nBase = blockIdx.y * 128;
    float acc[4][4][4];
    #pragma unroll
    for (int mt = 0; mt < 4; mt++)
        #pragma unroll
        for (int nt = 0; nt < 4; nt++)
            #pragma unroll
            for (int e = 0; e < 4; e++) acc[mt][nt][e] = 0.f;

    const int nIter = (3 * Cin) >> 5;
    const int ar = tid >> 1;
    const int ac = (tid & 1) * 2;
    uint32_t sA0 = smem_u32(&As[0][0]);
    uint32_t sB0 = smem_u32(&Bs[0][0]);

    #define LOAD_SLAB(IT, BUF)                                                     \
    do {                                                                           \
        int k0 = (IT) << 5;                                                        \
        int seg = k0 / Cin;                                                        \
        int kin = k0 - seg * Cin;                                                  \
        const bf16* Ap = (seg == 1) ? Al : Ah;                                     \
        const bf16* Bp = (seg == 2) ? Wl : Wh;                                     \
        uint32_t adst = sA0 + (BUF) * 10240 + (ar * 40 + ac * 8) * 2;              \
        uint32_t bdst = sB0 + (BUF) * 10240 + (ar * 40 + ac * 8) * 2;              \
        cpasync16(adst,      Ap + (size_t)(jBase + ar) * lda + kin + ac * 8);      \
        cpasync16(adst + 16, Ap + (size_t)(jBase + ar) * lda + kin + ac * 8 + 8);  \
        cpasync16(bdst,      Bp + (size_t)(nBase + ar) * ldw + kin + ac * 8);      \
        cpasync16(bdst + 16, Bp + (size_t)(nBase + ar) * ldw + kin + ac * 8 + 8);  \
    } while (0)

    LOAD_SLAB(0, 0);
    cpcommit();
    cpwait<0>();
    __syncthreads();

    for (int it = 0; it < nIter; it++) {
        int cur = it & 1;
        if (it + 1 < nIter) {
            LOAD_SLAB(it + 1, cur ^ 1);
            cpcommit();
        }
        uint32_t sA = sA0 + cur * 10240;
        uint32_t sB = sB0 + cur * 10240;
        #pragma unroll
        for (int s = 0; s < 2; s++) {
            uint32_t afr[4][4];
            uint32_t bfr[4][2];
            #pragma unroll
            for (int mt = 0; mt < 4; mt++) {
                uint32_t addrA = sA + ((warpM * 64 + mt * 16 + (lane & 15)) * 40) * 2
                               + s * 32 + ((lane >> 4) << 4);
                ldsm_x4(afr[mt][0], afr[mt][1], afr[mt][2], afr[mt][3], addrA);
            }
            #pragma unroll
            for (int nt = 0; nt < 4; nt++) {
                uint32_t addrB = sB + ((warpN * 32 + nt * 8 + (lane & 7)) * 40) * 2
                               + s * 32 + (((lane >> 3) & 1) << 4);
                ldsm_x2(bfr[nt][0], bfr[nt][1], addrB);
            }
            #pragma unroll
            for (int mt = 0; mt < 4; mt++)
                #pragma unroll
                for (int nt = 0; nt < 4; nt++)
                    mma16816(acc[mt][nt], afr[mt], bfr[nt]);
        }
        if (it + 1 < nIter) {
            cpwait<0>();
            __syncthreads();
        }
    }
    #undef LOAD_SLAB

    #pragma unroll
    for (int mt = 0; mt < 4; mt++) {
        int m = jBase + warpM * 64 + mt * 16 + (lane >> 2);
        int bd0 = (m / 6144) * 3 + (m % 3);
        int m8 = m + 8;
        int bd1 = (m8 / 6144) * 3 + (m8 % 3);
        #pragma unroll
        for (int nt = 0; nt < 4; nt++) {
            int n = nBase + warpN * 32 + nt * 8 + (lane & 3) * 2;
            float b00 = 0.f, b01 = 0.f, b10 = 0.f, b11 = 0.f;
            if (bias) {
                b00 = bias[bd0 * 256 + n];     b01 = bias[bd0 * 256 + n + 1];
                b10 = bias[bd1 * 256 + n];     b11 = bias[bd1 * 256 + n + 1];
            }
            *(float2*)&C[(size_t)m * ldc + n] =
                make_float2(acc[mt][nt][0] + b00, acc[mt][nt][1] + b01);
            *(float2*)&C[(size_t)m8 * ldc + n] =
                make_float2(acc[mt][nt][2] + b10, acc[mt][nt][3] + b11);
        }
    }
}

// ---------------- vec_lna pointwise epilogue (2 bn per block) ----------------
__global__ __launch_bounds__(256)
void pointwise_kernel(const float* __restrict__ Cbuf,
                      bf16* __restrict__ dstH, bf16* __restrict__ dstL,
                      int ldd, int off) {
    __shared__ float sred[2][4];
    int half = threadIdx.x >> 7;
    int c = threadIdx.x & 127;
    int wih = (threadIdx.x >> 5) & 3;
    int lane = threadIdx.x & 31;
    int bn = blockIdx.x * 2 + half;
    int j0 = bn * 3;
    float ux = Cbuf[(size_t)(j0 + 0) * 256 + c];
    float uy = Cbuf[(size_t)(j0 + 1) * 256 + c];
    float uz = Cbuf[(size_t)(j0 + 2) * 256 + c];
    float kx = Cbuf[(size_t)(j0 + 0) * 256 + 128 + c];
    float ky = Cbuf[(size_t)(j0 + 1) * 256 + 128 + c];
    float kz = Cbuf[(size_t)(j0 + 2) * 256 + 128 + c];
    float v = ux * ux + uy * uy + uz * uz;
    #pragma unroll
    for (int o = 16; o > 0; o >>= 1) v += __shfl_xor_sync(0xffffffffu, v, o);
    if (lane == 0) sred[half][wih] = v;
    __syncthreads();
    float tot = sred[half][0] + sred[half][1] + sred[half][2] + sred[half][3];
    float s = 1.f / fmaxf(sqrtf(tot), EPSf);
    float kl = sqrtf(kx * kx + ky * ky + kz * kz);
    float ki = 1.f / fmaxf(kl, EPSf);
    kx *= ki; ky *= ki; kz *= ki;
    float dot = s * (ux * kx + uy * ky + uz * kz);
    float neg = fminf(dot, 0.f);
    split2(s * ux - neg * kx, dstH[(size_t)(j0 + 0) * ldd + off + c], dstL[(size_t)(j0 + 0) * ldd + off + c]);
    split2(s * uy - neg * ky, dstH[(size_t)(j0 + 1) * ldd + off + c], dstL[(size_t)(j0 + 1) * ldd + off + c]);
    split2(s * uz - neg * kz, dstH[(size_t)(j0 + 2) * ldd + off + c], dstL[(size_t)(j0 + 2) * ldd + off + c]);
}

// ---------------- single-kernel mean over N of h1 (X2, pitch 128) ----------------
__global__ __launch_bounds__(1024)
void meanN_kernel() {
    __shared__ float part[8][128];
    int bd = blockIdx.x;                 // 0..23
    int b = bd / 3, d = bd % 3;
    int c = threadIdx.x & 127;
    int slab = threadIdx.x >> 7;         // 0..7 (256 n each)
    size_t base = ((size_t)(b * Npts + slab * 256) * 3 + d) * 128 + c;
    float s = 0.f;
    #pragma unroll 8
    for (int n = 0; n < 256; n++) {
        size_t a = base + (size_t)n * 384;
        s += __bfloat162float(g_X2h[a]) + __bfloat162float(g_X2l[a]);
    }
    part[slab][c] = s;
    __syncthreads();
    if (threadIdx.x < 128) {
        float t = 0.f;
        #pragma unroll
        for (int p = 0; p < 8; p++) t += part[p][c];
        g_gmean[bd * Hc + c] = t;
    }
}

// ---------------- bias from the g-half: bias[bd][o] = sum_c GW[o][128+c]*gmean[bd][c]/N ----
__global__ __launch_bounds__(256)
void bias_kernel(const bf16* __restrict__ GWh, const bf16* __restrict__ GWl) {
    __shared__ float gm[128];
    int bd = blockIdx.x;
    int o = threadIdx.x;
    if (o < 128) gm[o] = g_gmean[bd * Hc + o] * (1.f / (float)Npts);
    __syncthreads();
    const bf16* rh = GWh + (size_t)o * 256 + 128;
    const bf16* rl = GWl + (size_t)o * 256 + 128;
    float s = 0.f;
    #pragma unroll 8
    for (int c = 0; c < 128; c++)
        s += (__bfloat162float(rh[c]) + __bfloat162float(rl[c])) * gm[c];
    g_bias[bd * 256 + o] = s;
}

// ---------------- coalesced tiled-transpose writeout ----------------
__global__ __launch_bounds__(256)
void writeout_kernel(float* __restrict__ out, int big_off) {
    __shared__ float tile[32][33];
    int tx = threadIdx.x & 31;
    int ty = threadIdx.x >> 5;
    int n0 = blockIdx.x * 32;
    int o0 = blockIdx.y * 32;
    int bd = blockIdx.z;
    int b = bd / 3, d = bd % 3;
    #pragma unroll
    for (int i = 0; i < 4; i++) {
        int n = n0 + ty + i * 8;
        tile[ty + i * 8][tx] = g_C[(((size_t)(b * Npts + n)) * 3 + d) * 128 + o0 + tx];
    }
    __syncthreads();
    #pragma unroll
    for (int i = 0; i < 4; i++) {
        int o = o0 + ty + i * 8;
        out[big_off + (((size_t)(b * 128 + o)) * 3 + d) * Npts + n0 + tx] = tile[tx][ty + i * 8];
    }
}

__global__ void meanout_kernel(float* __restrict__ out, int big_off, int mean_off) {
    int w = blockIdx.x * 8 + (threadIdx.x >> 5);
    int lane = threadIdx.x & 31;
    const float* base = out + big_off + (size_t)w * Npts;
    float s = 0.f;
    #pragma unroll 8
    for (int i = lane; i < Npts; i += 32) s += base[i];
    #pragma unroll
    for (int o = 16; o > 0; o >>= 1) s += __shfl_xor_sync(0xffffffffu, s, o);
    if (lane == 0) out[mean_off + w] = s * (1.f / (float)Npts);
}

// ---------------- host launcher ----------------
extern "C" void kernel_launch(void* const* d_in, const int* in_sizes, int n_in,
                              void* d_out, int out_size) {
    const float* x     = (const float*)d_in[0];
    const float* W_in  = (const float*)d_in[1];
    const float* Wd_in = (const float*)d_in[2];
    const float* Ws    = (const float*)d_in[3];
    const float* Wds   = (const float*)d_in[4];
    const float* Gs    = (const float*)d_in[5];
    const float* Gds   = (const float*)d_in[6];
    const float* W_out = (const float*)d_in[7];
    float* out = (float*)d_out;

    float *pC, *pBias;
    bf16 *pX0h, *pX0l, *pX2h, *pX2l, *pFTh, *pFTl, *pUKh, *pUKl, *pGWh, *pGWl, *pOWh, *pOWl;
    cudaGetSymbolAddress((void**)&pC, g_C);
    cudaGetSymbolAddress((void**)&pBias, g_bias);
    cudaGetSymbolAddress((void**)&pX0h, g_X0h);
    cudaGetSymbolAddress((void**)&pX0l, g_X0l);
    cudaGetSymbolAddress((void**)&pX2h, g_X2h);
    cudaGetSymbolAddress((void**)&pX2l, g_X2l);
    cudaGetSymbolAddress((void**)&pFTh, g_FTh);
    cudaGetSymbolAddress((void**)&pFTl, g_FTl);
    cudaGetSymbolAddress((void**)&pUKh, g_UKh);
    cudaGetSymbolAddress((void**)&pUKl, g_UKl);
    cudaGetSymbolAddress((void**)&pGWh, g_GWh);
    cudaGetSymbolAddress((void**)&pGWl, g_GWl);
    cudaGetSymbolAddress((void**)&pOWh, g_OWh);
    cudaGetSymbolAddress((void**)&pOWl, g_OWl);

    int mean_off = 0, big_off = 0;
    bool has_mean = true;
    const int BIG = Bsz * CDc * 3 * Npts;
    const int MEAN = Bsz * CDc * 3;
    if (out_size >= BIG + MEAN) { mean_off = 0; big_off = MEAN; }
    else { big_off = 0; has_mean = false; }

    const int prepTot = 384 + Lc * 256 * 128 + Lc * 256 * 256 + 128 * 512;
    prep_kernel<<<(prepTot + 255) / 256, 256>>>(W_in, Wd_in, Ws, Wds, Gs, Gds, W_out);
    knn_kernel<<<Bsz * 8, 256>>>(x);
    stage2_kernel<<<NBlk, 128>>>(x, W_in);

    const bf16* Xh = pX0h;
    const bf16* Xl = pX0l;
    int lda = Hc;
    dim3 g2(Jtot / 128, 2), g1(Jtot / 128, 1);
    for (int i = 0; i < Lc; i++) {
        // U/Kr = [Ws;Mw] @ h
        gemm_bf16<<<g2, 256>>>(Xh, Xl, lda, 128,
                               pUKh + (size_t)i * 256 * 128, pUKl + (size_t)i * 256 * 128, 128,
                               pC, 256, nullptr);
        pointwise_kernel<<<NBlk / 2, 256>>>(pC, pX2h, pX2l, 128, 0);
        meanN_kernel<<<24, 1024>>>();
        bias_kernel<<<24, 256>>>(pGWh + (size_t)i * 256 * 256, pGWl + (size_t)i * 256 * 256);
        // U/Kr = [GsA;MGA] @ h1 + bias(g-half)
        gemm_bf16<<<g2, 256>>>(pX2h, pX2l, 128, 128,
                               pGWh + (size_t)i * 256 * 256, pGWl + (size_t)i * 256 * 256, 256,
                               pC, 256, pBias);
        pointwise_kernel<<<NBlk / 2, 256>>>(pC, pFTh, pFTl, 512, i * 128);
        Xh = pFTh + (size_t)i * 128;
        Xl = pFTl + (size_t)i * 128;
        lda = 512;
    }
    gemm_bf16<<<g1, 256>>>(pFTh, pFTl, 512, 512, pOWh, pOWl, 512, pC, 128, nullptr);
    writeout_kernel<<<dim3(Npts / 32, 4, 24), 256>>>(out, big_off);
    if (has_mean) meanout_kernel<<<384, 256>>>(out, big_off, mean_off);
}